// round 13
// baseline (speedup 1.0000x reference)
#include <cuda_runtime.h>

#define NB 32
#define NP 256
#define ND 64
#define NT 4096
#define NPART 256          // partials per (b,p): 16 chunks x 4 warps x 4 groups

#define NEG_HALF_LOG2E (-0.72134752044448170f)   // -0.5 * log2(e)

typedef unsigned long long u64;

// pred[b*NP+p][t] materialized by sgemm (128 MB)
__device__ float  g_pred[(size_t)NB * NP * NT];
// Per-8-lane-group partials: (warp max m [log2 units], S, V, pad)
__device__ float4 g_part[(size_t)NB * NP * NPART];

// ---------- packed f32x2 helpers ----------
__device__ __forceinline__ u64 fma2(u64 a, u64 b, u64 acc) {
    u64 r;
    asm("fma.rn.f32x2 %0, %1, %2, %3;" : "=l"(r) : "l"(a), "l"(b), "l"(acc));
    return r;
}
__device__ __forceinline__ u64 pack2(float x, float y) {
    u64 r;
    asm("mov.b64 %0, {%1, %2};" : "=l"(r) : "f"(x), "f"(y));
    return r;
}

// Warp float-max for values <= 0 in ONE instruction (u32-min over raw bits;
// +0.0 -> 0x00000000, negatives order inversely as u32).
__device__ __forceinline__ float warp_max_nonpos(float x) {
    return __uint_as_float(__reduce_min_sync(0xffffffffu, __float_as_uint(x)));
}

// 2^x via MUFU (logits kept in log2 domain).
__device__ __forceinline__ float ex2f(float x) {
    float r;
    asm("ex2.approx.f32 %0, %1;" : "=f"(r) : "f"(x));
    return r;
}

// ------------------------------------------------------------------
// SGEMM: pred = data (8192 x 64) @ task_pool^T (64 x 4096), fp32 exact.
// 128x128 tile per CTA, K=64 resident in smem (single load phase).
// Each thread: 8x8 frag (2x4 m, 2x4 n), packed-FMA2 accumulators.
// ------------------------------------------------------------------
__global__ void __launch_bounds__(256, 2)
sgemm(const float* __restrict__ data, const float* __restrict__ tp)
{
    __shared__ float As[ND][132];   // [k][m], pad 4 (LDS.128-aligned rows)
    __shared__ float Bs[ND][132];   // [k][n]

    const int tid  = threadIdx.x;
    const int mblk = blockIdx.y * 128;
    const int nblk = blockIdx.x * 128;

    // Load + transpose tiles (once; K=64 total).
    const float4* ag = (const float4*)(data + (size_t)mblk * ND);
    const float4* bg = (const float4*)(tp   + (size_t)nblk * ND);
    #pragma unroll
    for (int j = 0; j < 8; ++j) {
        const int idx = tid + 256 * j;   // float4 index within 128x64 tile
        const int r   = idx >> 4;        // row (m or n)
        const int k4  = idx & 15;        // float4 index along k
        float4 v = __ldg(ag + idx);
        As[k4 * 4 + 0][r] = v.x; As[k4 * 4 + 1][r] = v.y;
        As[k4 * 4 + 2][r] = v.z; As[k4 * 4 + 3][r] = v.w;
        float4 w = __ldg(bg + idx);
        Bs[k4 * 4 + 0][r] = w.x; Bs[k4 * 4 + 1][r] = w.y;
        Bs[k4 * 4 + 2][r] = w.z; Bs[k4 * 4 + 3][r] = w.w;
    }
    __syncthreads();

    const int tx = tid & 15;    // n-index
    const int ty = tid >> 4;    // m-index

    // c2[ii][i4][jj][jp]: packed pairs of n-adjacent accumulators
    u64 c2[2][4][2][2];
    #pragma unroll
    for (int ii = 0; ii < 2; ++ii)
        #pragma unroll
        for (int i4 = 0; i4 < 4; ++i4)
            #pragma unroll
            for (int jj = 0; jj < 2; ++jj) {
                c2[ii][i4][jj][0] = 0ull;
                c2[ii][i4][jj][1] = 0ull;
            }

    #pragma unroll 8
    for (int k = 0; k < ND; ++k) {
        const float4 a0 = *(const float4*)&As[k][ty * 4];
        const float4 a1 = *(const float4*)&As[k][ty * 4 + 64];
        const ulonglong2 b0 = *(const ulonglong2*)&Bs[k][tx * 4];
        const ulonglong2 b1 = *(const ulonglong2*)&Bs[k][tx * 4 + 64];

        u64 aa[2][4];
        aa[0][0] = pack2(a0.x, a0.x); aa[0][1] = pack2(a0.y, a0.y);
        aa[0][2] = pack2(a0.z, a0.z); aa[0][3] = pack2(a0.w, a0.w);
        aa[1][0] = pack2(a1.x, a1.x); aa[1][1] = pack2(a1.y, a1.y);
        aa[1][2] = pack2(a1.z, a1.z); aa[1][3] = pack2(a1.w, a1.w);

        #pragma unroll
        for (int ii = 0; ii < 2; ++ii)
            #pragma unroll
            for (int i4 = 0; i4 < 4; ++i4) {
                c2[ii][i4][0][0] = fma2(aa[ii][i4], b0.x, c2[ii][i4][0][0]);
                c2[ii][i4][0][1] = fma2(aa[ii][i4], b0.y, c2[ii][i4][0][1]);
                c2[ii][i4][1][0] = fma2(aa[ii][i4], b1.x, c2[ii][i4][1][0]);
                c2[ii][i4][1][1] = fma2(aa[ii][i4], b1.y, c2[ii][i4][1][1]);
            }
    }

    // Epilogue: coalesced STG.128 (lanes tx*4 -> 16B apart).
    #pragma unroll
    for (int ii = 0; ii < 2; ++ii)
        #pragma unroll
        for (int i4 = 0; i4 < 4; ++i4) {
            const int m = mblk + ty * 4 + i4 + 64 * ii;
            float* orow = g_pred + (size_t)m * NT + nblk;
            #pragma unroll
            for (int jj = 0; jj < 2; ++jj) {
                ulonglong2 v;
                v.x = c2[ii][i4][jj][0];
                v.y = c2[ii][i4][jj][1];
                *(ulonglong2*)(orow + tx * 4 + 64 * jj) = v;
            }
        }
}

// ------------------------------------------------------------------
// Scan: CTA = (t-chunk of 256, b), 128 threads, 2 tasks/thread.
// Depth-4 prefetch ring over pred rows (loads independent of scan).
// Per p: redux max, 2x ex2, 8-lane-group (S,V) partials (3 SHFL levels).
// ------------------------------------------------------------------
__global__ void __launch_bounds__(128)
scan(const float* __restrict__ targets)
{
    const int chunk = blockIdx.x;   // 0..15
    const int b     = blockIdx.y;
    const int tid   = threadIdx.x;
    const int lane  = tid & 31;
    const int warp  = tid >> 5;

    __shared__ float stgt[NP];
    stgt[tid]       = targets[b * NP + tid];
    stgt[tid + 128] = targets[b * NP + tid + 128];
    __syncthreads();

    // pred row base for this thread's task pair (float2 granularity)
    const float2* pb = (const float2*)(g_pred + (size_t)b * NP * NT)
                     + chunk * 128 + tid;            // col = chunk*256 + 2*tid

    float4* mypart = g_part + ((size_t)b * NP) * NPART
                   + chunk * 16 + warp * 4 + (lane >> 3);

    float2 ring[4];
    #pragma unroll
    for (int u = 0; u < 4; ++u) ring[u] = __ldg(pb + (size_t)u * (NT / 2));

    float cA = 0.0f, cB = 0.0f;   // prefix cumsums, log2 units (<= 0)

    #pragma unroll 1
    for (int p0 = 0; p0 < NP; p0 += 4) {
        #pragma unroll
        for (int u = 0; u < 4; ++u) {
            const int p = p0 + u;
            const float2 pr = ring[u];
            if (p + 4 < NP)
                ring[u] = __ldg(pb + (size_t)(p + 4) * (NT / 2));

            const float lA = cA, lB = cB;
            const float tg = stgt[p];
            const float eA = tg - pr.x;
            const float eB = tg - pr.y;
            cA = fmaf(NEG_HALF_LOG2E * eA, eA, cA);
            cB = fmaf(NEG_HALF_LOG2E * eB, eB, cB);

            const float m  = warp_max_nonpos(fmaxf(lA, lB));
            const float sA = ex2f(lA - m);   // warp leader -> exactly 1
            const float sB = ex2f(lB - m);
            float S = sA + sB;
            float V = fmaf(sA, pr.x, sB * pr.y);
            #pragma unroll
            for (int off = 1; off <= 4; off <<= 1) {
                S += __shfl_xor_sync(0xffffffffu, S, off);
                V += __shfl_xor_sync(0xffffffffu, V, off);
            }
            if ((lane & 7) == 0)
                mypart[(size_t)p * NPART] = make_float4(m, S, V, 0.0f);
        }
    }
}

// ------------------------------------------------------------------
// Combine: one warp per (b,p); LSE-merge its 256 group partials.
// ------------------------------------------------------------------
__global__ void __launch_bounds__(256)
mmse_combine(float* __restrict__ out)
{
    const int warp = threadIdx.x >> 5;
    const int lane = threadIdx.x & 31;
    const int idx  = blockIdx.x * 8 + warp;    // b*NP + p
    const float4* pp = g_part + (size_t)idx * NPART;

    float4 l[8];
    #pragma unroll
    for (int j = 0; j < 8; ++j)
        l[j] = pp[lane + 32 * j];

    float mx = l[0].x;
    #pragma unroll
    for (int j = 1; j < 8; ++j) mx = fmaxf(mx, l[j].x);
    mx = warp_max_nonpos(mx);       // all m's <= 0

    float S = 0.0f, V = 0.0f;
    #pragma unroll
    for (int j = 0; j < 8; ++j) {
        const float e = ex2f(l[j].x - mx);
        S = fmaf(e, l[j].y, S);
        V = fmaf(e, l[j].z, V);
    }
    #pragma unroll
    for (int off = 16; off > 0; off >>= 1) {
        S += __shfl_xor_sync(0xffffffffu, S, off);
        V += __shfl_xor_sync(0xffffffffu, V, off);
    }

    if (lane == 0) out[idx] = V / S;
}

// ------------------------------------------------------------------
extern "C" void kernel_launch(void* const* d_in, const int* in_sizes, int n_in,
                              void* d_out, int out_size)
{
    (void)out_size;
    const float* data      = (const float*)d_in[0];
    const float* targets   = (const float*)d_in[1];
    const float* task_pool = (const float*)d_in[2];
    for (int i = 0; i < n_in; ++i) {
        if (in_sizes[i] == NB * NP * ND)      data      = (const float*)d_in[i];
        else if (in_sizes[i] == NB * NP)      targets   = (const float*)d_in[i];
        else if (in_sizes[i] == NT * ND)      task_pool = (const float*)d_in[i];
    }
    float* out = (float*)d_out;   // (B, P)

    sgemm<<<dim3(NT / 128, (NB * NP) / 128), 256>>>(data, task_pool);
    scan<<<dim3(16, NB), 128>>>(targets);
    mmse_combine<<<(NB * NP) / 8, 256>>>(out);
}

// round 15
// speedup vs baseline: 1.3790x; 1.3790x over previous
#include <cuda_runtime.h>
#include <cuda_bf16.h>
#include <cstdint>

#define NB 32
#define NP 256
#define ND 64
#define NT 4096
#define NPART 128          // partials per (b,p): 8 chunks x 4 warps x 4 groups

#define NEG_HALF_LOG2E (-0.72134752044448170f)   // -0.5 * log2(e)

typedef unsigned long long u64;

// pred[b*NP+p][t] materialized by tc_gemm (128 MB)
__device__ float  g_pred[(size_t)NB * NP * NT];
// Per-8-lane-group partials: (max m [log2 units], S, V, pad)
__device__ float4 g_part[(size_t)NB * NP * NPART];

// ---------------- helpers ----------------
__device__ __forceinline__ uint32_t smem_u32(const void* p) {
    uint32_t a;
    asm("{ .reg .u64 t; cvta.to.shared.u64 t, %1; cvt.u32.u64 %0, t; }"
        : "=r"(a) : "l"(p));
    return a;
}
__device__ __forceinline__ float warp_max_nonpos(float x) {
    return __uint_as_float(__reduce_min_sync(0xffffffffu, __float_as_uint(x)));
}
__device__ __forceinline__ float ex2f(float x) {
    float r;
    asm("ex2.approx.f32 %0, %1;" : "=f"(r) : "f"(x));
    return r;
}

#define LDMX4(r0, r1, r2, r3, addr)                                        \
    asm volatile("ldmatrix.sync.aligned.m8n8.x4.shared.b16 {%0,%1,%2,%3}, [%4];" \
                 : "=r"(r0), "=r"(r1), "=r"(r2), "=r"(r3) : "r"(addr))

__device__ __forceinline__ void mma_bf16(float* c, const uint32_t* a,
                                         const uint32_t* b) {
    asm volatile(
        "mma.sync.aligned.m16n8k16.row.col.f32.bf16.bf16.f32 "
        "{%0,%1,%2,%3}, {%4,%5,%6,%7}, {%8,%9}, {%0,%1,%2,%3};"
        : "+f"(c[0]), "+f"(c[1]), "+f"(c[2]), "+f"(c[3])
        : "r"(a[0]), "r"(a[1]), "r"(a[2]), "r"(a[3]), "r"(b[0]), "r"(b[1]));
}

// ------------------------------------------------------------------
// tc_gemm: pred = data (8192 x 64) @ task_pool^T via mma.sync bf16
// 2-term split (D = Ah*Bh + Ah*Bl + Al*Bh, fp32 accumulate).
// CTA tile 128x128, K=64 resident in smem (stride 72 bf16 = 144 B,
// odd multiple of 16 B -> conflict-free ldmatrix). 8 warps, each a
// 32x64 warp tile (2 m-frags x 8 n-frags), 4 k-steps of 16.
// ------------------------------------------------------------------
#define SSTR 72   // smem row stride in bf16

__global__ void __launch_bounds__(256)
tc_gemm(const float* __restrict__ data, const float* __restrict__ tp)
{
    __shared__ __nv_bfloat16 Ah[128][SSTR], Al[128][SSTR];
    __shared__ __nv_bfloat16 Bh[128][SSTR], Bl[128][SSTR];

    const int tid  = threadIdx.x;
    const int wid  = tid >> 5;
    const int lane = tid & 31;
    const int mblk = blockIdx.y * 128;
    const int nblk = blockIdx.x * 128;

    // Load + split: A tile (128x64) and B tile (128x64)
    const float4* ag = (const float4*)(data + (size_t)mblk * ND);
    const float4* bg = (const float4*)(tp   + (size_t)nblk * ND);
    #pragma unroll
    for (int j = 0; j < 8; ++j) {
        const int idx = tid + 256 * j;   // float4 index in 128x16
        const int r   = idx >> 4;
        const int c   = (idx & 15) * 4;  // bf16 column
        {
            const float4 v = __ldg(ag + idx);
            __nv_bfloat16 hx = __float2bfloat16_rn(v.x), hy = __float2bfloat16_rn(v.y);
            __nv_bfloat16 hz = __float2bfloat16_rn(v.z), hw = __float2bfloat16_rn(v.w);
            Ah[r][c] = hx; Ah[r][c + 1] = hy; Ah[r][c + 2] = hz; Ah[r][c + 3] = hw;
            Al[r][c]     = __float2bfloat16_rn(v.x - __bfloat162float(hx));
            Al[r][c + 1] = __float2bfloat16_rn(v.y - __bfloat162float(hy));
            Al[r][c + 2] = __float2bfloat16_rn(v.z - __bfloat162float(hz));
            Al[r][c + 3] = __float2bfloat16_rn(v.w - __bfloat162float(hw));
        }
        {
            const float4 v = __ldg(bg + idx);
            __nv_bfloat16 hx = __float2bfloat16_rn(v.x), hy = __float2bfloat16_rn(v.y);
            __nv_bfloat16 hz = __float2bfloat16_rn(v.z), hw = __float2bfloat16_rn(v.w);
            Bh[r][c] = hx; Bh[r][c + 1] = hy; Bh[r][c + 2] = hz; Bh[r][c + 3] = hw;
            Bl[r][c]     = __float2bfloat16_rn(v.x - __bfloat162float(hx));
            Bl[r][c + 1] = __float2bfloat16_rn(v.y - __bfloat162float(hy));
            Bl[r][c + 2] = __float2bfloat16_rn(v.z - __bfloat162float(hz));
            Bl[r][c + 3] = __float2bfloat16_rn(v.w - __bfloat162float(hw));
        }
    }
    __syncthreads();

    const int warpM = wid & 3;          // m offset = 32*warpM
    const int warpN = wid >> 2;         // n offset = 64*warpN
    const int r8    = lane & 7;
    const int quad  = lane >> 3;

    float acc[2][8][4];
    #pragma unroll
    for (int mt = 0; mt < 2; ++mt)
        #pragma unroll
        for (int nt = 0; nt < 8; ++nt)
            #pragma unroll
            for (int q = 0; q < 4; ++q) acc[mt][nt][q] = 0.0f;

    #pragma unroll
    for (int ks = 0; ks < 4; ++ks) {
        const int k0 = ks * 16;

        // A fragments (16x16 each): matrices (m0,k0),(m0+8,k0),(m0,k0+8),(m0+8,k0+8)
        uint32_t ah[2][4], al[2][4];
        #pragma unroll
        for (int mt = 0; mt < 2; ++mt) {
            const int row = warpM * 32 + mt * 16 + r8 + (quad & 1) * 8;
            const int col = k0 + (quad >> 1) * 8;
            LDMX4(ah[mt][0], ah[mt][1], ah[mt][2], ah[mt][3],
                  smem_u32(&Ah[row][col]));
            LDMX4(al[mt][0], al[mt][1], al[mt][2], al[mt][3],
                  smem_u32(&Al[row][col]));
        }

        // B fragments: x4 = two n-tiles; matrices (n0,k0),(n0,k0+8),(n0+8,k0),(n0+8,k0+8)
        uint32_t bh[8][2], bl[8][2];
        #pragma unroll
        for (int nt2 = 0; nt2 < 4; ++nt2) {
            const int row = warpN * 64 + nt2 * 16 + r8 + (quad >> 1) * 8;
            const int col = k0 + (quad & 1) * 8;
            LDMX4(bh[2 * nt2][0], bh[2 * nt2][1], bh[2 * nt2 + 1][0], bh[2 * nt2 + 1][1],
                  smem_u32(&Bh[row][col]));
            LDMX4(bl[2 * nt2][0], bl[2 * nt2][1], bl[2 * nt2 + 1][0], bl[2 * nt2 + 1][1],
                  smem_u32(&Bl[row][col]));
        }

        #pragma unroll
        for (int mt = 0; mt < 2; ++mt)
            #pragma unroll
            for (int nt = 0; nt < 8; ++nt) {
                mma_bf16(acc[mt][nt], ah[mt], bh[nt]);
                mma_bf16(acc[mt][nt], ah[mt], bl[nt]);
                mma_bf16(acc[mt][nt], al[mt], bh[nt]);
            }
    }

    // Epilogue: c0,c1 -> (m=gid, col=2*tig), c2,c3 -> (m=gid+8, same col)
    const int gid = lane >> 2;
    const int tig = lane & 3;
    #pragma unroll
    for (int mt = 0; mt < 2; ++mt) {
        const int m0 = mblk + warpM * 32 + mt * 16 + gid;
        #pragma unroll
        for (int nt = 0; nt < 8; ++nt) {
            const int col = nblk + warpN * 64 + nt * 8 + tig * 2;
            float2 v0 = make_float2(acc[mt][nt][0], acc[mt][nt][1]);
            float2 v1 = make_float2(acc[mt][nt][2], acc[mt][nt][3]);
            *(float2*)(g_pred + (size_t)m0 * NT + col)       = v0;
            *(float2*)(g_pred + (size_t)(m0 + 8) * NT + col) = v1;
        }
    }
}

// ------------------------------------------------------------------
// Scan: CTA = (t-chunk of 512, b), 128 threads, 4 tasks/thread.
// Depth-8 prefetch ring over pred rows. Per p: redux max, 4x ex2,
// 8-lane-group (S,V) partials (3 SHFL levels). Log2-domain logits.
// ------------------------------------------------------------------
__global__ void __launch_bounds__(128)
scan(const float* __restrict__ targets)
{
    const int chunk = blockIdx.x;   // 0..7
    const int b     = blockIdx.y;
    const int tid   = threadIdx.x;
    const int lane  = tid & 31;
    const int warp  = tid >> 5;

    __shared__ float stgt[NP];
    stgt[tid]       = targets[b * NP + tid];
    stgt[tid + 128] = targets[b * NP + tid + 128];
    __syncthreads();

    // 4 consecutive tasks per thread: cols chunk*512 + 4*tid ..+3
    const float4* pb = (const float4*)(g_pred + (size_t)b * NP * NT)
                     + chunk * 128 + tid;

    float4* mypart = g_part + ((size_t)b * NP) * NPART
                   + chunk * 16 + warp * 4 + (lane >> 3);

    float4 ring[8];
    #pragma unroll
    for (int u = 0; u < 8; ++u) ring[u] = __ldg(pb + (size_t)u * (NT / 4));

    float cA = 0.0f, cB = 0.0f, cC = 0.0f, cD = 0.0f;   // log2-domain (<= 0)

    #pragma unroll 1
    for (int p0 = 0; p0 < NP; p0 += 8) {
        #pragma unroll
        for (int u = 0; u < 8; ++u) {
            const int p = p0 + u;
            const float4 pr = ring[u];
            if (p + 8 < NP)
                ring[u] = __ldg(pb + (size_t)(p + 8) * (NT / 4));

            const float lA = cA, lB = cB, lC = cC, lD = cD;
            const float tg = stgt[p];
            const float eA = tg - pr.x;
            const float eB = tg - pr.y;
            const float eC = tg - pr.z;
            const float eD = tg - pr.w;
            cA = fmaf(NEG_HALF_LOG2E * eA, eA, cA);
            cB = fmaf(NEG_HALF_LOG2E * eB, eB, cB);
            cC = fmaf(NEG_HALF_LOG2E * eC, eC, cC);
            cD = fmaf(NEG_HALF_LOG2E * eD, eD, cD);

            const float m = warp_max_nonpos(
                fmaxf(fmaxf(lA, lB), fmaxf(lC, lD)));
            const float sA = ex2f(lA - m);   // warp leader -> exactly 1
            const float sB = ex2f(lB - m);
            const float sC = ex2f(lC - m);
            const float sD = ex2f(lD - m);
            float S = (sA + sB) + (sC + sD);
            float V = fmaf(sA, pr.x, sB * pr.y) + fmaf(sC, pr.z, sD * pr.w);
            #pragma unroll
            for (int off = 1; off <= 4; off <<= 1) {
                S += __shfl_xor_sync(0xffffffffu, S, off);
                V += __shfl_xor_sync(0xffffffffu, V, off);
            }
            if ((lane & 7) == 0)
                mypart[(size_t)p * NPART] = make_float4(m, S, V, 0.0f);
        }
    }
}

// ------------------------------------------------------------------
// Combine: one warp per (b,p); LSE-merge its 128 group partials.
// ------------------------------------------------------------------
__global__ void __launch_bounds__(256)
mmse_combine(float* __restrict__ out)
{
    const int warp = threadIdx.x >> 5;
    const int lane = threadIdx.x & 31;
    const int idx  = blockIdx.x * 8 + warp;    // b*NP + p
    const float4* pp = g_part + (size_t)idx * NPART;

    float4 l[4];
    #pragma unroll
    for (int j = 0; j < 4; ++j)
        l[j] = pp[lane + 32 * j];

    float mx = fmaxf(fmaxf(l[0].x, l[1].x), fmaxf(l[2].x, l[3].x));
    mx = warp_max_nonpos(mx);       // all m's <= 0

    float S = 0.0f, V = 0.0f;
    #pragma unroll
    for (int j = 0; j < 4; ++j) {
        const float e = ex2f(l[j].x - mx);
        S = fmaf(e, l[j].y, S);
        V = fmaf(e, l[j].z, V);
    }
    #pragma unroll
    for (int off = 16; off > 0; off >>= 1) {
        S += __shfl_xor_sync(0xffffffffu, S, off);
        V += __shfl_xor_sync(0xffffffffu, V, off);
    }

    if (lane == 0) out[idx] = V / S;
}

// ------------------------------------------------------------------
extern "C" void kernel_launch(void* const* d_in, const int* in_sizes, int n_in,
                              void* d_out, int out_size)
{
    (void)out_size;
    const float* data      = (const float*)d_in[0];
    const float* targets   = (const float*)d_in[1];
    const float* task_pool = (const float*)d_in[2];
    for (int i = 0; i < n_in; ++i) {
        if (in_sizes[i] == NB * NP * ND)      data      = (const float*)d_in[i];
        else if (in_sizes[i] == NB * NP)      targets   = (const float*)d_in[i];
        else if (in_sizes[i] == NT * ND)      task_pool = (const float*)d_in[i];
    }
    float* out = (float*)d_out;   // (B, P)

    tc_gemm<<<dim3(NT / 128, (NB * NP) / 128), 256>>>(data, task_pool);
    scan<<<dim3(8, NB), 128>>>(targets);
    mmse_combine<<<(NB * NP) / 8, 256>>>(out);
}

// round 16
// speedup vs baseline: 1.6186x; 1.1737x over previous
#include <cuda_runtime.h>
#include <cuda_bf16.h>
#include <cstdint>

#define NB 32
#define NP 256
#define ND 64
#define NT 4096
#define NPART 128          // partials per (b,p): 8 chunks x 4 warps x 4 groups

#define NEG_HALF_LOG2E (-0.72134752044448170f)   // -0.5 * log2(e)

typedef unsigned long long u64;

// pred[b*NP+p][t] materialized by tc_gemm (128 MB, mostly L2-resident)
__device__ float  g_pred[(size_t)NB * NP * NT];
// Per-8-lane-group partials: (max m [log2 units], S, V, pad)
__device__ float4 g_part[(size_t)NB * NP * NPART];

// ---------------- helpers ----------------
__device__ __forceinline__ uint32_t smem_u32(const void* p) {
    uint32_t a;
    asm("{ .reg .u64 t; cvta.to.shared.u64 t, %1; cvt.u32.u64 %0, t; }"
        : "=r"(a) : "l"(p));
    return a;
}
__device__ __forceinline__ float warp_max_nonpos(float x) {
    return __uint_as_float(__reduce_min_sync(0xffffffffu, __float_as_uint(x)));
}
__device__ __forceinline__ float ex2f(float x) {
    float r;
    asm("ex2.approx.f32 %0, %1;" : "=f"(r) : "f"(x));
    return r;
}

#define LDMX4(r0, r1, r2, r3, addr)                                        \
    asm volatile("ldmatrix.sync.aligned.m8n8.x4.shared.b16 {%0,%1,%2,%3}, [%4];" \
                 : "=r"(r0), "=r"(r1), "=r"(r2), "=r"(r3) : "r"(addr))

__device__ __forceinline__ void mma_bf16(float* c, const uint32_t* a,
                                         const uint32_t* b) {
    asm volatile(
        "mma.sync.aligned.m16n8k16.row.col.f32.bf16.bf16.f32 "
        "{%0,%1,%2,%3}, {%4,%5,%6,%7}, {%8,%9}, {%0,%1,%2,%3};"
        : "+f"(c[0]), "+f"(c[1]), "+f"(c[2]), "+f"(c[3])
        : "r"(a[0]), "r"(a[1]), "r"(a[2]), "r"(a[3]), "r"(b[0]), "r"(b[1]));
}

// ------------------------------------------------------------------
// tc_gemm: pred = data (8192 x 64) @ task_pool^T via mma.sync bf16
// 2-term split (D = Ah*Bh + Ah*Bl + Al*Bh, fp32 accumulate).
// CTA tile 128x128, K=64 resident (stride 72 bf16 -> conflict-free
// ldmatrix). 8 warps x (32x64) warp tiles. __launch_bounds__(256,2):
// 128-reg cap => 2 CTAs/SM so load/MMA/epilogue phases overlap across
// CTAs. B fragments loaded in 4 nt2-slices to keep live regs ~110.
// ------------------------------------------------------------------
#define SSTR 72   // smem row stride in bf16

__global__ void __launch_bounds__(256, 2)
tc_gemm(const float* __restrict__ data, const float* __restrict__ tp)
{
    __shared__ __nv_bfloat16 Ah[128][SSTR], Al[128][SSTR];
    __shared__ __nv_bfloat16 Bh[128][SSTR], Bl[128][SSTR];

    const int tid  = threadIdx.x;
    const int wid  = tid >> 5;
    const int lane = tid & 31;
    const int mblk = blockIdx.y * 128;
    const int nblk = blockIdx.x * 128;

    // Load + split: A tile (128x64) and B tile (128x64)
    const float4* ag = (const float4*)(data + (size_t)mblk * ND);
    const float4* bg = (const float4*)(tp   + (size_t)nblk * ND);
    #pragma unroll
    for (int j = 0; j < 8; ++j) {
        const int idx = tid + 256 * j;   // float4 index in 128x16
        const int r   = idx >> 4;
        const int c   = (idx & 15) * 4;  // bf16 column
        {
            const float4 v = __ldg(ag + idx);
            __nv_bfloat16 hx = __float2bfloat16_rn(v.x), hy = __float2bfloat16_rn(v.y);
            __nv_bfloat16 hz = __float2bfloat16_rn(v.z), hw = __float2bfloat16_rn(v.w);
            Ah[r][c] = hx; Ah[r][c + 1] = hy; Ah[r][c + 2] = hz; Ah[r][c + 3] = hw;
            Al[r][c]     = __float2bfloat16_rn(v.x - __bfloat162float(hx));
            Al[r][c + 1] = __float2bfloat16_rn(v.y - __bfloat162float(hy));
            Al[r][c + 2] = __float2bfloat16_rn(v.z - __bfloat162float(hz));
            Al[r][c + 3] = __float2bfloat16_rn(v.w - __bfloat162float(hw));
        }
        {
            const float4 v = __ldg(bg + idx);
            __nv_bfloat16 hx = __float2bfloat16_rn(v.x), hy = __float2bfloat16_rn(v.y);
            __nv_bfloat16 hz = __float2bfloat16_rn(v.z), hw = __float2bfloat16_rn(v.w);
            Bh[r][c] = hx; Bh[r][c + 1] = hy; Bh[r][c + 2] = hz; Bh[r][c + 3] = hw;
            Bl[r][c]     = __float2bfloat16_rn(v.x - __bfloat162float(hx));
            Bl[r][c + 1] = __float2bfloat16_rn(v.y - __bfloat162float(hy));
            Bl[r][c + 2] = __float2bfloat16_rn(v.z - __bfloat162float(hz));
            Bl[r][c + 3] = __float2bfloat16_rn(v.w - __bfloat162float(hw));
        }
    }
    __syncthreads();

    const int warpM = wid & 3;          // m offset = 32*warpM
    const int warpN = wid >> 2;         // n offset = 64*warpN
    const int r8    = lane & 7;
    const int quad  = lane >> 3;

    float acc[2][8][4];
    #pragma unroll
    for (int mt = 0; mt < 2; ++mt)
        #pragma unroll
        for (int nt = 0; nt < 8; ++nt)
            #pragma unroll
            for (int q = 0; q < 4; ++q) acc[mt][nt][q] = 0.0f;

    #pragma unroll
    for (int ks = 0; ks < 4; ++ks) {
        const int k0 = ks * 16;

        // A fragments (16x16): matrices (m0,k0),(m0+8,k0),(m0,k0+8),(m0+8,k0+8)
        uint32_t ah[2][4], al[2][4];
        #pragma unroll
        for (int mt = 0; mt < 2; ++mt) {
            const int row = warpM * 32 + mt * 16 + r8 + (quad & 1) * 8;
            const int col = k0 + (quad >> 1) * 8;
            LDMX4(ah[mt][0], ah[mt][1], ah[mt][2], ah[mt][3],
                  smem_u32(&Ah[row][col]));
            LDMX4(al[mt][0], al[mt][1], al[mt][2], al[mt][3],
                  smem_u32(&Al[row][col]));
        }

        // B fragments in 4 slices of 2 n-tiles: only 8 B-regs live at a time
        #pragma unroll
        for (int nt2 = 0; nt2 < 4; ++nt2) {
            const int row = warpN * 64 + nt2 * 16 + r8 + (quad >> 1) * 8;
            const int col = k0 + (quad & 1) * 8;
            uint32_t bh[2][2], bl[2][2];
            LDMX4(bh[0][0], bh[0][1], bh[1][0], bh[1][1],
                  smem_u32(&Bh[row][col]));
            LDMX4(bl[0][0], bl[0][1], bl[1][0], bl[1][1],
                  smem_u32(&Bl[row][col]));

            #pragma unroll
            for (int j = 0; j < 2; ++j) {
                const int nt = 2 * nt2 + j;
                #pragma unroll
                for (int mt = 0; mt < 2; ++mt) {
                    mma_bf16(acc[mt][nt], ah[mt], bh[j]);
                    mma_bf16(acc[mt][nt], ah[mt], bl[j]);
                    mma_bf16(acc[mt][nt], al[mt], bh[j]);
                }
            }
        }
    }

    // Epilogue: c0,c1 -> (m=gid, col=2*tig), c2,c3 -> (m=gid+8, same col)
    const int gid = lane >> 2;
    const int tig = lane & 3;
    #pragma unroll
    for (int mt = 0; mt < 2; ++mt) {
        const int m0 = mblk + warpM * 32 + mt * 16 + gid;
        #pragma unroll
        for (int nt = 0; nt < 8; ++nt) {
            const int col = nblk + warpN * 64 + nt * 8 + tig * 2;
            float2 v0 = make_float2(acc[mt][nt][0], acc[mt][nt][1]);
            float2 v1 = make_float2(acc[mt][nt][2], acc[mt][nt][3]);
            *(float2*)(g_pred + (size_t)m0 * NT + col)       = v0;
            *(float2*)(g_pred + (size_t)(m0 + 8) * NT + col) = v1;
        }
    }
}

// ------------------------------------------------------------------
// Scan: CTA = (t-chunk of 512, b), 128 threads, 4 tasks/thread.
// Depth-8 prefetch ring over pred rows. Per p: redux max, 4x ex2,
// 8-lane-group (S,V) partials (3 SHFL levels). Log2-domain logits.
// ------------------------------------------------------------------
__global__ void __launch_bounds__(128)
scan(const float* __restrict__ targets)
{
    const int chunk = blockIdx.x;   // 0..7
    const int b     = blockIdx.y;
    const int tid   = threadIdx.x;
    const int lane  = tid & 31;
    const int warp  = tid >> 5;

    __shared__ float stgt[NP];
    stgt[tid]       = targets[b * NP + tid];
    stgt[tid + 128] = targets[b * NP + tid + 128];
    __syncthreads();

    const float4* pb = (const float4*)(g_pred + (size_t)b * NP * NT)
                     + chunk * 128 + tid;

    float4* mypart = g_part + ((size_t)b * NP) * NPART
                   + chunk * 16 + warp * 4 + (lane >> 3);

    float4 ring[8];
    #pragma unroll
    for (int u = 0; u < 8; ++u) ring[u] = __ldg(pb + (size_t)u * (NT / 4));

    float cA = 0.0f, cB = 0.0f, cC = 0.0f, cD = 0.0f;   // log2-domain (<= 0)

    #pragma unroll 1
    for (int p0 = 0; p0 < NP; p0 += 8) {
        #pragma unroll
        for (int u = 0; u < 8; ++u) {
            const int p = p0 + u;
            const float4 pr = ring[u];
            if (p + 8 < NP)
                ring[u] = __ldg(pb + (size_t)(p + 8) * (NT / 4));

            const float lA = cA, lB = cB, lC = cC, lD = cD;
            const float tg = stgt[p];
            const float eA = tg - pr.x;
            const float eB = tg - pr.y;
            const float eC = tg - pr.z;
            const float eD = tg - pr.w;
            cA = fmaf(NEG_HALF_LOG2E * eA, eA, cA);
            cB = fmaf(NEG_HALF_LOG2E * eB, eB, cB);
            cC = fmaf(NEG_HALF_LOG2E * eC, eC, cC);
            cD = fmaf(NEG_HALF_LOG2E * eD, eD, cD);

            const float m = warp_max_nonpos(
                fmaxf(fmaxf(lA, lB), fmaxf(lC, lD)));
            const float sA = ex2f(lA - m);   // warp leader -> exactly 1
            const float sB = ex2f(lB - m);
            const float sC = ex2f(lC - m);
            const float sD = ex2f(lD - m);
            float S = (sA + sB) + (sC + sD);
            float V = fmaf(sA, pr.x, sB * pr.y) + fmaf(sC, pr.z, sD * pr.w);
            #pragma unroll
            for (int off = 1; off <= 4; off <<= 1) {
                S += __shfl_xor_sync(0xffffffffu, S, off);
                V += __shfl_xor_sync(0xffffffffu, V, off);
            }
            if ((lane & 7) == 0)
                mypart[(size_t)p * NPART] = make_float4(m, S, V, 0.0f);
        }
    }
}

// ------------------------------------------------------------------
// Combine: one warp per (b,p); LSE-merge its 128 group partials.
// ------------------------------------------------------------------
__global__ void __launch_bounds__(256)
mmse_combine(float* __restrict__ out)
{
    const int warp = threadIdx.x >> 5;
    const int lane = threadIdx.x & 31;
    const int idx  = blockIdx.x * 8 + warp;    // b*NP + p
    const float4* pp = g_part + (size_t)idx * NPART;

    float4 l[4];
    #pragma unroll
    for (int j = 0; j < 4; ++j)
        l[j] = pp[lane + 32 * j];

    float mx = fmaxf(fmaxf(l[0].x, l[1].x), fmaxf(l[2].x, l[3].x));
    mx = warp_max_nonpos(mx);       // all m's <= 0

    float S = 0.0f, V = 0.0f;
    #pragma unroll
    for (int j = 0; j < 4; ++j) {
        const float e = ex2f(l[j].x - mx);
        S = fmaf(e, l[j].y, S);
        V = fmaf(e, l[j].z, V);
    }
    #pragma unroll
    for (int off = 16; off > 0; off >>= 1) {
        S += __shfl_xor_sync(0xffffffffu, S, off);
        V += __shfl_xor_sync(0xffffffffu, V, off);
    }

    if (lane == 0) out[idx] = V / S;
}

// ------------------------------------------------------------------
extern "C" void kernel_launch(void* const* d_in, const int* in_sizes, int n_in,
                              void* d_out, int out_size)
{
    (void)out_size;
    const float* data      = (const float*)d_in[0];
    const float* targets   = (const float*)d_in[1];
    const float* task_pool = (const float*)d_in[2];
    for (int i = 0; i < n_in; ++i) {
        if (in_sizes[i] == NB * NP * ND)      data      = (const float*)d_in[i];
        else if (in_sizes[i] == NB * NP)      targets   = (const float*)d_in[i];
        else if (in_sizes[i] == NT * ND)      task_pool = (const float*)d_in[i];
    }
    float* out = (float*)d_out;   // (B, P)

    tc_gemm<<<dim3(NT / 128, (NB * NP) / 128), 256>>>(data, task_pool);
    scan<<<dim3(8, NB), 128>>>(targets);
    mmse_combine<<<(NB * NP) / 8, 256>>>(out);
}

// round 17
// speedup vs baseline: 1.9426x; 1.2002x over previous
#include <cuda_runtime.h>
#include <cuda_bf16.h>
#include <cstdint>

#define NB 32
#define NP 256
#define ND 64
#define NT 4096
#define NPART 128          // partials per (b,p): 8 chunks x 4 warps x 4 groups

#define NEG_HALF_LOG2E (-0.72134752044448170f)   // -0.5 * log2(e)

typedef unsigned long long u64;

// pred[b*NP+p][t] materialized by tc_gemm (128 MB, mostly L2-resident)
__device__ float  g_pred[(size_t)NB * NP * NT];
// Per-8-lane-group partials: (max m [log2 units], S, V, pad)
__device__ float4 g_part[(size_t)NB * NP * NPART];

// ---------------- helpers ----------------
__device__ __forceinline__ uint32_t smem_u32(const void* p) {
    uint32_t a;
    asm("{ .reg .u64 t; cvta.to.shared.u64 t, %1; cvt.u32.u64 %0, t; }"
        : "=r"(a) : "l"(p));
    return a;
}
__device__ __forceinline__ float warp_max_nonpos(float x) {
    return __uint_as_float(__reduce_min_sync(0xffffffffu, __float_as_uint(x)));
}
__device__ __forceinline__ float ex2f(float x) {
    float r;
    asm("ex2.approx.f32 %0, %1;" : "=f"(r) : "f"(x));
    return r;
}

#define LDMX4(r0, r1, r2, r3, addr)                                        \
    asm volatile("ldmatrix.sync.aligned.m8n8.x4.shared.b16 {%0,%1,%2,%3}, [%4];" \
                 : "=r"(r0), "=r"(r1), "=r"(r2), "=r"(r3) : "r"(addr))

__device__ __forceinline__ void mma_bf16(float* c, const uint32_t* a,
                                         const uint32_t* b) {
    asm volatile(
        "mma.sync.aligned.m16n8k16.row.col.f32.bf16.bf16.f32 "
        "{%0,%1,%2,%3}, {%4,%5,%6,%7}, {%8,%9}, {%0,%1,%2,%3};"
        : "+f"(c[0]), "+f"(c[1]), "+f"(c[2]), "+f"(c[3])
        : "r"(a[0]), "r"(a[1]), "r"(a[2]), "r"(a[3]), "r"(b[0]), "r"(b[1]));
}

// ---- mbarrier / bulk-copy (sm_90 baseline PTX; legal on plain sm_103) ----
#define MBAR_INIT(a, n) \
    asm volatile("mbarrier.init.shared.b64 [%0], %1;" \
                 :: "r"((uint32_t)(a)), "r"((uint32_t)(n)) : "memory")
#define MBAR_EXPECT_TX(a, bytes) \
    asm volatile("mbarrier.arrive.expect_tx.shared.b64 _, [%0], %1;" \
                 :: "r"((uint32_t)(a)), "r"((uint32_t)(bytes)) : "memory")
#define MBAR_WAIT(a, par) do {                                                   \
    asm volatile("{\n\t.reg .pred P1;\n\tWAIT_%=:\n\t"                           \
        "mbarrier.try_wait.parity.acquire.cta.shared::cta.b64 P1, [%0], %1, 0x989680;\n\t" \
        "@P1 bra.uni DONE_%=;\n\tbra.uni WAIT_%=;\n\tDONE_%=:\n\t}"              \
        :: "r"((uint32_t)(a)), "r"((uint32_t)(par)) : "memory");                 \
} while (0)
#define BULK_G2S(dst, src, bytes, mbar) \
    asm volatile("cp.async.bulk.shared::cluster.global.mbarrier::complete_tx::bytes " \
                 "[%0], [%1], %2, [%3];" \
                 :: "r"((uint32_t)(dst)), "l"(src), "r"((uint32_t)(bytes)), \
                    "r"((uint32_t)(mbar)) : "memory")

// ------------------------------------------------------------------
// tc_gemm: pred = data (8192 x 64) @ task_pool^T via mma.sync bf16
// 2-term split (D = Ah*Bh + Ah*Bl + Al*Bh, fp32 accumulate).
// CTA tile 128x128, K=64 resident (stride 72 bf16 -> conflict-free
// ldmatrix). 8 warps x (32x64). launch_bounds(256,2) -> 2 CTAs/SM.
// (unchanged from the passing 106.5us round)
// ------------------------------------------------------------------
#define SSTR 72   // smem row stride in bf16

__global__ void __launch_bounds__(256, 2)
tc_gemm(const float* __restrict__ data, const float* __restrict__ tp)
{
    __shared__ __nv_bfloat16 Ah[128][SSTR], Al[128][SSTR];
    __shared__ __nv_bfloat16 Bh[128][SSTR], Bl[128][SSTR];

    const int tid  = threadIdx.x;
    const int wid  = tid >> 5;
    const int lane = tid & 31;
    const int mblk = blockIdx.y * 128;
    const int nblk = blockIdx.x * 128;

    const float4* ag = (const float4*)(data + (size_t)mblk * ND);
    const float4* bg = (const float4*)(tp   + (size_t)nblk * ND);
    #pragma unroll
    for (int j = 0; j < 8; ++j) {
        const int idx = tid + 256 * j;   // float4 index in 128x16
        const int r   = idx >> 4;
        const int c   = (idx & 15) * 4;  // bf16 column
        {
            const float4 v = __ldg(ag + idx);
            __nv_bfloat16 hx = __float2bfloat16_rn(v.x), hy = __float2bfloat16_rn(v.y);
            __nv_bfloat16 hz = __float2bfloat16_rn(v.z), hw = __float2bfloat16_rn(v.w);
            Ah[r][c] = hx; Ah[r][c + 1] = hy; Ah[r][c + 2] = hz; Ah[r][c + 3] = hw;
            Al[r][c]     = __float2bfloat16_rn(v.x - __bfloat162float(hx));
            Al[r][c + 1] = __float2bfloat16_rn(v.y - __bfloat162float(hy));
            Al[r][c + 2] = __float2bfloat16_rn(v.z - __bfloat162float(hz));
            Al[r][c + 3] = __float2bfloat16_rn(v.w - __bfloat162float(hw));
        }
        {
            const float4 v = __ldg(bg + idx);
            __nv_bfloat16 hx = __float2bfloat16_rn(v.x), hy = __float2bfloat16_rn(v.y);
            __nv_bfloat16 hz = __float2bfloat16_rn(v.z), hw = __float2bfloat16_rn(v.w);
            Bh[r][c] = hx; Bh[r][c + 1] = hy; Bh[r][c + 2] = hz; Bh[r][c + 3] = hw;
            Bl[r][c]     = __float2bfloat16_rn(v.x - __bfloat162float(hx));
            Bl[r][c + 1] = __float2bfloat16_rn(v.y - __bfloat162float(hy));
            Bl[r][c + 2] = __float2bfloat16_rn(v.z - __bfloat162float(hz));
            Bl[r][c + 3] = __float2bfloat16_rn(v.w - __bfloat162float(hw));
        }
    }
    __syncthreads();

    const int warpM = wid & 3;
    const int warpN = wid >> 2;
    const int r8    = lane & 7;
    const int quad  = lane >> 3;

    float acc[2][8][4];
    #pragma unroll
    for (int mt = 0; mt < 2; ++mt)
        #pragma unroll
        for (int nt = 0; nt < 8; ++nt)
            #pragma unroll
            for (int q = 0; q < 4; ++q) acc[mt][nt][q] = 0.0f;

    #pragma unroll
    for (int ks = 0; ks < 4; ++ks) {
        const int k0 = ks * 16;

        uint32_t ah[2][4], al[2][4];
        #pragma unroll
        for (int mt = 0; mt < 2; ++mt) {
            const int row = warpM * 32 + mt * 16 + r8 + (quad & 1) * 8;
            const int col = k0 + (quad >> 1) * 8;
            LDMX4(ah[mt][0], ah[mt][1], ah[mt][2], ah[mt][3],
                  smem_u32(&Ah[row][col]));
            LDMX4(al[mt][0], al[mt][1], al[mt][2], al[mt][3],
                  smem_u32(&Al[row][col]));
        }

        #pragma unroll
        for (int nt2 = 0; nt2 < 4; ++nt2) {
            const int row = warpN * 64 + nt2 * 16 + r8 + (quad >> 1) * 8;
            const int col = k0 + (quad & 1) * 8;
            uint32_t bh[2][2], bl[2][2];
            LDMX4(bh[0][0], bh[0][1], bh[1][0], bh[1][1],
                  smem_u32(&Bh[row][col]));
            LDMX4(bl[0][0], bl[0][1], bl[1][0], bl[1][1],
                  smem_u32(&Bl[row][col]));

            #pragma unroll
            for (int j = 0; j < 2; ++j) {
                const int nt = 2 * nt2 + j;
                #pragma unroll
                for (int mt = 0; mt < 2; ++mt) {
                    mma_bf16(acc[mt][nt], ah[mt], bh[j]);
                    mma_bf16(acc[mt][nt], ah[mt], bl[j]);
                    mma_bf16(acc[mt][nt], al[mt], bh[j]);
                }
            }
        }
    }

    const int gid = lane >> 2;
    const int tig = lane & 3;
    #pragma unroll
    for (int mt = 0; mt < 2; ++mt) {
        const int m0 = mblk + warpM * 32 + mt * 16 + gid;
        #pragma unroll
        for (int nt = 0; nt < 8; ++nt) {
            const int col = nblk + warpN * 64 + nt * 8 + tig * 2;
            float2 v0 = make_float2(acc[mt][nt][0], acc[mt][nt][1]);
            float2 v1 = make_float2(acc[mt][nt][2], acc[mt][nt][3]);
            *(float2*)(g_pred + (size_t)m0 * NT + col)       = v0;
            *(float2*)(g_pred + (size_t)(m0 + 8) * NT + col) = v1;
        }
    }
}

// ------------------------------------------------------------------
// Scan: CTA = (t-chunk of 512, b), 128 threads, 4 tasks/thread.
// pred rows arrive via cp.async.bulk into a double-buffered smem
// stage (8 rows x 2KB per stage) -> removes the per-thread LDG issue
// floor. Consumers read conflict-free LDS.128.
// ------------------------------------------------------------------
#define SROWS 8                      // rows per stage
#define NSTG  (NP / SROWS)           // 32 stages
#define STG_BYTES (SROWS * 512 * 4)  // 16 KB per stage

__global__ void __launch_bounds__(128)
scan(const float* __restrict__ targets)
{
    __shared__ float buf[2][SROWS][512];
    __shared__ alignas(8) u64 mbar[2];

    const int chunk = blockIdx.x;   // 0..7
    const int b     = blockIdx.y;
    const int tid   = threadIdx.x;
    const int lane  = tid & 31;
    const int warp  = tid >> 5;

    __shared__ float stgt[NP];
    stgt[tid]       = targets[b * NP + tid];
    stgt[tid + 128] = targets[b * NP + tid + 128];

    const uint32_t mb0 = smem_u32(&mbar[0]);
    const uint32_t mb1 = smem_u32(&mbar[1]);
    if (tid == 0) { MBAR_INIT(mb0, 1); MBAR_INIT(mb1, 1); }
    __syncthreads();

    // global base of this CTA's 512-task column slice
    const char* gsrc = (const char*)(g_pred + (size_t)b * NP * NT + chunk * 512);

    // issue stage s into buffer bi
    auto issue = [&](int s, int bi) {
        const uint32_t mb = bi ? mb1 : mb0;
        MBAR_EXPECT_TX(mb, STG_BYTES);
        const uint32_t dst = smem_u32(&buf[bi][0][0]);
        #pragma unroll
        for (int r = 0; r < SROWS; ++r)
            BULK_G2S(dst + r * 2048,
                     gsrc + (size_t)(s * SROWS + r) * (NT * 4), 2048, mb);
    };
    if (tid == 0) { issue(0, 0); issue(1, 1); }

    float4* mypart = g_part + ((size_t)b * NP) * NPART
                   + chunk * 16 + warp * 4 + (lane >> 3);

    float cA = 0.0f, cB = 0.0f, cC = 0.0f, cD = 0.0f;   // log2-domain (<= 0)

    #pragma unroll 1
    for (int st = 0; st < NSTG; ++st) {
        const int bi = st & 1;
        MBAR_WAIT(bi ? mb1 : mb0, (st >> 1) & 1);

        #pragma unroll
        for (int r = 0; r < SROWS; ++r) {
            const int p = st * SROWS + r;
            const float4 pr = *(const float4*)&buf[bi][r][tid * 4];

            const float lA = cA, lB = cB, lC = cC, lD = cD;
            const float tg = stgt[p];
            const float eA = tg - pr.x;
            const float eB = tg - pr.y;
            const float eC = tg - pr.z;
            const float eD = tg - pr.w;
            cA = fmaf(NEG_HALF_LOG2E * eA, eA, cA);
            cB = fmaf(NEG_HALF_LOG2E * eB, eB, cB);
            cC = fmaf(NEG_HALF_LOG2E * eC, eC, cC);
            cD = fmaf(NEG_HALF_LOG2E * eD, eD, cD);

            const float m = warp_max_nonpos(
                fmaxf(fmaxf(lA, lB), fmaxf(lC, lD)));
            const float sA = ex2f(lA - m);   // warp leader -> exactly 1
            const float sB = ex2f(lB - m);
            const float sC = ex2f(lC - m);
            const float sD = ex2f(lD - m);
            float S = (sA + sB) + (sC + sD);
            float V = fmaf(sA, pr.x, sB * pr.y) + fmaf(sC, pr.z, sD * pr.w);
            #pragma unroll
            for (int off = 1; off <= 4; off <<= 1) {
                S += __shfl_xor_sync(0xffffffffu, S, off);
                V += __shfl_xor_sync(0xffffffffu, V, off);
            }
            if ((lane & 7) == 0)
                mypart[(size_t)p * NPART] = make_float4(m, S, V, 0.0f);
        }

        __syncthreads();                    // stage consumed by all threads
        if (tid == 0 && st + 2 < NSTG) issue(st + 2, bi);
    }
}

// ------------------------------------------------------------------
// Combine: one warp per (b,p); LSE-merge its 128 group partials.
// ------------------------------------------------------------------
__global__ void __launch_bounds__(256)
mmse_combine(float* __restrict__ out)
{
    const int warp = threadIdx.x >> 5;
    const int lane = threadIdx.x & 31;
    const int idx  = blockIdx.x * 8 + warp;    // b*NP + p
    const float4* pp = g_part + (size_t)idx * NPART;

    float4 l[4];
    #pragma unroll
    for (int j = 0; j < 4; ++j)
        l[j] = pp[lane + 32 * j];

    float mx = fmaxf(fmaxf(l[0].x, l[1].x), fmaxf(l[2].x, l[3].x));
    mx = warp_max_nonpos(mx);       // all m's <= 0

    float S = 0.0f, V = 0.0f;
    #pragma unroll
    for (int j = 0; j < 4; ++j) {
        const float e = ex2f(l[j].x - mx);
        S = fmaf(e, l[j].y, S);
        V = fmaf(e, l[j].z, V);
    }
    #pragma unroll
    for (int off = 16; off > 0; off >>= 1) {
        S += __shfl_xor_sync(0xffffffffu, S, off);
        V += __shfl_xor_sync(0xffffffffu, V, off);
    }

    if (lane == 0) out[idx] = V / S;
}

// ------------------------------------------------------------------
extern "C" void kernel_launch(void* const* d_in, const int* in_sizes, int n_in,
                              void* d_out, int out_size)
{
    (void)out_size;
    const float* data      = (const float*)d_in[0];
    const float* targets   = (const float*)d_in[1];
    const float* task_pool = (const float*)d_in[2];
    for (int i = 0; i < n_in; ++i) {
        if (in_sizes[i] == NB * NP * ND)      data      = (const float*)d_in[i];
        else if (in_sizes[i] == NB * NP)      targets   = (const float*)d_in[i];
        else if (in_sizes[i] == NT * ND)      task_pool = (const float*)d_in[i];
    }
    float* out = (float*)d_out;   // (B, P)

    tc_gemm<<<dim3(NT / 128, (NB * NP) / 128), 256>>>(data, task_pool);
    scan<<<dim3(8, NB), 128>>>(targets);
    mmse_combine<<<(NB * NP) / 8, 256>>>(out);
}